// round 13
// baseline (speedup 1.0000x reference)
#include <cuda_runtime.h>
#include <cuda_bf16.h>
#include <cstdint>

// Problem constants: T=2048, N=64, D=1024
#define T_DIM 2048
#define N_DIM 64
#define D_VEC 256                 // float4 per row
#define VEC_PER_LANE 8            // 256 / 32 lanes
#define NWARPS 4
#define NTHREADS 128
#define NBX 32                    // 32 blocks * 4 warps = 128 streams per sequence
#define NSTREAMS 128              // rows t = s + 128*k belong to stream s
#define NSTAGES 2
#define HALF_LOG_2PI 0.91893853320467274178f
#define EPS_VAR 1e-6f

// Cross-block reduction state. g_cnt starts at 0 (static init) and is reset
// to 0 by the finishing block every launch -> deterministic across replays.
__device__ float g_partial[N_DIM][NBX];
__device__ int   g_cnt[N_DIM];

__device__ __forceinline__ void cp_async16(unsigned int saddr, const void* gptr) {
    asm volatile("cp.async.cg.shared.global [%0], [%1], 16;\n"
                 :: "r"(saddr), "l"(gptr));
}
__device__ __forceinline__ void cp_commit() {
    asm volatile("cp.async.commit_group;\n" ::: "memory");
}
__device__ __forceinline__ void cp_wait1() {
    asm volatile("cp.async.wait_group 1;\n" ::: "memory");
}

// 5 blocks/SM (regs<=102 target, smem 5x33KB=165KB < 228KB): 20 streams/SM.
__global__ __launch_bounds__(NTHREADS, 5)
void gnll_kernel(const float* __restrict__ y,     // (T, N)
                 const float4* __restrict__ x4,   // (T, N, D/4)
                 const float4* __restrict__ W4,   // (2, D/4)
                 const int* __restrict__ lens,    // (N,)
                 float* __restrict__ out)         // (N,)
{
    // Per-warp private double buffer: 2 stages x 4KB per warp.
    __shared__ float4 buf[NWARPS][NSTAGES][D_VEC];
    __shared__ float  s_partial[NWARPS];

    const int n    = blockIdx.y;
    const int bx   = blockIdx.x;
    const int len  = lens[n];
    const int tid  = threadIdx.x;
    const int wid  = tid >> 5;
    const int lane = tid & 31;

    // Warp-private stream: rows t = s + 128*k, all strictly < len by kmax.
    const int s = bx * NWARPS + wid;               // 0..127, warp-uniform
    const int kmax = (len > s) ? ((len - s + NSTREAMS - 1) >> 7) : 0;

    float warp_sum = 0.0f;

    if (kmax > 0) {   // warp-uniform; cp.async accounting is per-thread so
                      // warps with no work may skip the pipeline entirely.
        // Preload W lane-striped into registers (64 regs).
        float4 w0[VEC_PER_LANE], w1[VEC_PER_LANE];
        #pragma unroll
        for (int i = 0; i < VEC_PER_LANE; i++) {
            w0[i] = W4[i * 32 + lane];
            w1[i] = W4[D_VEC + i * 32 + lane];
        }

        // Issue one full row (4KB) into this warp's stage st; one commit/call.
        // Lane l writes exactly the slots it later reads -> no __syncwarp.
        auto issue = [&](int k, int st) {
            const int t = s + (k << 7);
            const float4* g = x4 + ((size_t)t * N_DIM + n) * D_VEC + lane;
            unsigned int sb = (unsigned int)__cvta_generic_to_shared(&buf[wid][st][lane]);
            #pragma unroll
            for (int c = 0; c < VEC_PER_LANE; c++)
                cp_async16(sb + (unsigned int)c * 32u * 16u, g + c * 32);
            cp_commit();
        };

        issue(0, 0);
        if (kmax > 1) issue(1, 1); else cp_commit();

        for (int k = 0; k < kmax; k++) {
            cp_wait1();                          // tile k's group complete
            const int st = k & 1;
            const float4* src = &buf[wid][st][0];

            float a0 = 0.0f, a1 = 0.0f;
            #pragma unroll
            for (int i = 0; i < VEC_PER_LANE; i++) {
                float4 v = src[i * 32 + lane];
                a0 = fmaf(v.x, w0[i].x, a0);
                a0 = fmaf(v.y, w0[i].y, a0);
                a0 = fmaf(v.z, w0[i].z, a0);
                a0 = fmaf(v.w, w0[i].w, a0);
                a1 = fmaf(v.x, w1[i].x, a1);
                a1 = fmaf(v.y, w1[i].y, a1);
                a1 = fmaf(v.z, w1[i].z, a1);
                a1 = fmaf(v.w, w1[i].w, a1);
            }

            // Refill consumed stage before the reduce so the next DRAM fetch
            // overlaps the shuffle chain.
            if (k + NSTAGES < kmax) issue(k + NSTAGES, st); else cp_commit();

            #pragma unroll
            for (int off = 16; off > 0; off >>= 1) {
                a0 += __shfl_xor_sync(0xFFFFFFFFu, a0, off);
                a1 += __shfl_xor_sync(0xFFFFFFFFu, a1, off);
            }
            if (lane == 0) {
                const int t = s + (k << 7);
                float mu  = a0;
                float var = fmaxf(1.0f / (1.0f + __expf(-a1)), EPS_VAR);
                float d   = y[t * N_DIM + n] - mu;
                warp_sum += 0.5f * (__logf(var) + d * d / var) + HALF_LOG_2PI;
            }
        }
    }

    // Block reduce (all warps reach here, even kmax==0 ones).
    if (lane == 0) s_partial[wid] = warp_sum;
    __syncthreads();

    if (tid == 0) {
        float bs = s_partial[0] + s_partial[1] + s_partial[2] + s_partial[3];
        g_partial[n][bx] = bs;                 // always written, no init needed
        __threadfence();                       // release partial before ticket
        int old = atomicAdd(&g_cnt[n], 1);
        if (old == NBX - 1) {                  // last block for this n
            __threadfence();                   // acquire all partials
            float total = 0.0f;
            #pragma unroll
            for (int i = 0; i < NBX; i++) total += g_partial[n][i];
            out[n] = total;
            g_cnt[n] = 0;                      // reset for next (replayed) launch
        }
    }
}

extern "C" void kernel_launch(void* const* d_in, const int* in_sizes, int n_in,
                              void* d_out, int out_size) {
    // metadata order: y (T*N f32), x (T*N*D f32), W (2*D f32), lens (N i32)
    const float*  y    = (const float*)d_in[0];
    const float4* x4   = (const float4*)d_in[1];
    const float4* W4   = (const float4*)d_in[2];
    const int*    lens = (const int*)d_in[3];
    float*        out  = (float*)d_out;

    dim3 grid(NBX, N_DIM);
    dim3 block(NTHREADS);
    gnll_kernel<<<grid, block>>>(y, x4, W4, lens, out);
}

// round 14
// speedup vs baseline: 1.0177x; 1.0177x over previous
#include <cuda_runtime.h>
#include <cuda_bf16.h>
#include <cstdint>

// Problem constants: T=2048, N=64, D=1024
#define T_DIM 2048
#define N_DIM 64
#define D_VEC 256                 // float4 per row
#define VEC_PER_LANE 8            // 256 / 32 lanes
#define NWARPS 4
#define NTHREADS 128
#define NBX 32                    // 32 blocks * 4 warps = 128 streams per sequence
#define NSTREAMS 128              // rows t = s + 128*k belong to stream s
#define NSTAGES 2
#define HALF_LOG_2PI 0.91893853320467274178f
#define EPS_VAR 1e-6f

__device__ __forceinline__ void cp_async16(unsigned int saddr, const void* gptr) {
    asm volatile("cp.async.cg.shared.global [%0], [%1], 16;\n"
                 :: "r"(saddr), "l"(gptr));
}
__device__ __forceinline__ void cp_commit() {
    asm volatile("cp.async.commit_group;\n" ::: "memory");
}
__device__ __forceinline__ void cp_wait1() {
    asm volatile("cp.async.wait_group 1;\n" ::: "memory");
}

// 5 blocks/SM (regs<=102 target, smem 5x33KB=165KB < 228KB): 20 streams/SM.
__global__ __launch_bounds__(NTHREADS, 5)
void gnll_kernel(const float* __restrict__ y,     // (T, N)
                 const float4* __restrict__ x4,   // (T, N, D/4)
                 const float4* __restrict__ W4,   // (2, D/4)
                 const int* __restrict__ lens,    // (N,)
                 float* __restrict__ out)         // (N,)
{
    // Per-warp private double buffer: 2 stages x 4KB per warp. No block sync.
    __shared__ float4 buf[NWARPS][NSTAGES][D_VEC];

    const int n    = blockIdx.y;
    const int bx   = blockIdx.x;
    const int len  = lens[n];
    const int tid  = threadIdx.x;
    const int wid  = tid >> 5;
    const int lane = tid & 31;

    // Warp-private stream: rows t = s + 128*k, all strictly < len by kmax.
    const int s = bx * NWARPS + wid;               // 0..127, warp-uniform
    const int kmax = (len > s) ? ((len - s + NSTREAMS - 1) >> 7) : 0;
    if (kmax == 0) return;                         // warp-uniform exit

    // Preload W lane-striped into registers (64 regs).
    float4 w0[VEC_PER_LANE], w1[VEC_PER_LANE];
    #pragma unroll
    for (int i = 0; i < VEC_PER_LANE; i++) {
        w0[i] = W4[i * 32 + lane];
        w1[i] = W4[D_VEC + i * 32 + lane];
    }

    // Issue one full row (4KB) into this warp's stage st; one commit per call.
    // Lane l writes slots {c*32+l}; it later reads exactly those slots, so
    // per-thread wait_group suffices — no __syncwarp needed.
    auto issue = [&](int k, int st) {
        const int t = s + (k << 7);
        const float4* g = x4 + ((size_t)t * N_DIM + n) * D_VEC + lane;
        unsigned int sb = (unsigned int)__cvta_generic_to_shared(&buf[wid][st][lane]);
        #pragma unroll
        for (int c = 0; c < VEC_PER_LANE; c++)
            cp_async16(sb + (unsigned int)c * 32u * 16u, g + c * 32);
        cp_commit();
    };

    // Prologue: always exactly NSTAGES commits.
    issue(0, 0);
    if (kmax > 1) issue(1, 1); else cp_commit();

    float warp_sum = 0.0f;

    for (int k = 0; k < kmax; k++) {
        cp_wait1();                          // tile k's group complete
        const int st = k & 1;
        const float4* src = &buf[wid][st][0];

        float a0 = 0.0f, a1 = 0.0f;
        #pragma unroll
        for (int i = 0; i < VEC_PER_LANE; i++) {
            float4 v = src[i * 32 + lane];
            a0 = fmaf(v.x, w0[i].x, a0);
            a0 = fmaf(v.y, w0[i].y, a0);
            a0 = fmaf(v.z, w0[i].z, a0);
            a0 = fmaf(v.w, w0[i].w, a0);
            a1 = fmaf(v.x, w1[i].x, a1);
            a1 = fmaf(v.y, w1[i].y, a1);
            a1 = fmaf(v.z, w1[i].z, a1);
            a1 = fmaf(v.w, w1[i].w, a1);
        }

        // Refill the consumed stage immediately (before the reduce chain) so
        // the next tile's DRAM fetch overlaps the shuffle latency.
        if (k + NSTAGES < kmax) issue(k + NSTAGES, st); else cp_commit();

        #pragma unroll
        for (int off = 16; off > 0; off >>= 1) {
            a0 += __shfl_xor_sync(0xFFFFFFFFu, a0, off);
            a1 += __shfl_xor_sync(0xFFFFFFFFu, a1, off);
        }
        if (lane == 0) {
            const int t = s + (k << 7);
            float mu  = a0;
            float var = fmaxf(1.0f / (1.0f + __expf(-a1)), EPS_VAR);
            float d   = y[t * N_DIM + n] - mu;
            warp_sum += 0.5f * (__logf(var) + d * d / var) + HALF_LOG_2PI;
        }
    }

    if (lane == 0) atomicAdd(&out[n], warp_sum);
}

extern "C" void kernel_launch(void* const* d_in, const int* in_sizes, int n_in,
                              void* d_out, int out_size) {
    // metadata order: y (T*N f32), x (T*N*D f32), W (2*D f32), lens (N i32)
    const float*  y    = (const float*)d_in[0];
    const float4* x4   = (const float4*)d_in[1];
    const float4* W4   = (const float4*)d_in[2];
    const int*    lens = (const int*)d_in[3];
    float*        out  = (float*)d_out;

    // Zero the accumulator via a memset node (cheaper than a kernel node;
    // graph-capturable, no allocation). 0x00 bit pattern == 0.0f.
    cudaMemsetAsync(out, 0, N_DIM * sizeof(float));

    dim3 grid(NBX, N_DIM);
    dim3 block(NTHREADS);
    gnll_kernel<<<grid, block>>>(y, x4, W4, lens, out);
}

// round 16
// speedup vs baseline: 1.0602x; 1.0418x over previous
#include <cuda_runtime.h>
#include <cuda_bf16.h>
#include <cstdint>

// Problem constants: T=2048, N=64, D=1024
#define T_DIM 2048
#define N_DIM 64
#define D_VEC 256                 // float4 per row
#define VEC_PER_LANE 8            // 256 / 32 lanes
#define NWARPS 4
#define NTHREADS 128
#define NBX 32                    // 32 blocks * 4 warps = 128 streams per sequence
#define NSTREAMS 128              // rows t = s + 128*k belong to stream s
#define NSTAGES 2
#define HALF_LOG_2PI 0.91893853320467274178f
#define EPS_VAR 1e-6f

__device__ __forceinline__ void cp_async16(unsigned int saddr, const void* gptr) {
    asm volatile("cp.async.cg.shared.global [%0], [%1], 16;\n"
                 :: "r"(saddr), "l"(gptr));
}
__device__ __forceinline__ void cp_commit() {
    asm volatile("cp.async.commit_group;\n" ::: "memory");
}
__device__ __forceinline__ void cp_wait1() {
    asm volatile("cp.async.wait_group 1;\n" ::: "memory");
}

// 5 blocks/SM (regs<=102 target, smem 5x33KB=165KB < 228KB): 20 streams/SM.
__global__ __launch_bounds__(NTHREADS, 5)
void gnll_kernel(const float* __restrict__ y,     // (T, N)
                 const float4* __restrict__ x4,   // (T, N, D/4)
                 const float4* __restrict__ W4,   // (2, D/4)
                 const int* __restrict__ lens,    // (N,)
                 float* __restrict__ out)         // (N,)
{
    // Per-warp private double buffer: 2 stages x 4KB per warp. No block sync.
    __shared__ float4 buf[NWARPS][NSTAGES][D_VEC];

    const int n    = blockIdx.y;
    const int bx   = blockIdx.x;
    const int len  = lens[n];
    const int tid  = threadIdx.x;
    const int wid  = tid >> 5;
    const int lane = tid & 31;

    // Warp-private stream: rows t = s + 128*k, all strictly < len by kmax.
    const int s = bx * NWARPS + wid;               // 0..127, warp-uniform
    const int kmax = (len > s) ? ((len - s + NSTREAMS - 1) >> 7) : 0;
    if (kmax == 0) return;                         // warp-uniform exit

    // Preload W lane-striped into registers (64 regs).
    float4 w0[VEC_PER_LANE], w1[VEC_PER_LANE];
    #pragma unroll
    for (int i = 0; i < VEC_PER_LANE; i++) {
        w0[i] = W4[i * 32 + lane];
        w1[i] = W4[D_VEC + i * 32 + lane];
    }

    // Issue one full row (4KB) into this warp's stage st; one commit per call.
    // Lane l writes slots {c*32+l}; it later reads exactly those slots, so
    // per-thread wait_group suffices — no __syncwarp needed.
    auto issue = [&](int k, int st) {
        const int t = s + (k << 7);
        const float4* g = x4 + ((size_t)t * N_DIM + n) * D_VEC + lane;
        unsigned int sb = (unsigned int)__cvta_generic_to_shared(&buf[wid][st][lane]);
        #pragma unroll
        for (int c = 0; c < VEC_PER_LANE; c++)
            cp_async16(sb + (unsigned int)c * 32u * 16u, g + c * 32);
        cp_commit();
    };

    // Prologue: always exactly NSTAGES commits.
    issue(0, 0);
    if (kmax > 1) issue(1, 1); else cp_commit();

    float warp_sum = 0.0f;

    for (int k = 0; k < kmax; k++) {
        const int t = s + (k << 7);
        // Prefetch y for this tile NOW (independent of the smem tile): the
        // ~600-cycle load completes under the FMA+shuffle work instead of
        // stalling the post-reduce NLL. Same address across lanes = 1 sector.
        const float yv = __ldg(y + (size_t)t * N_DIM + n);

        cp_wait1();                          // tile k's group complete
        const int st = k & 1;
        const float4* src = &buf[wid][st][0];

        float a0 = 0.0f, a1 = 0.0f;
        #pragma unroll
        for (int i = 0; i < VEC_PER_LANE; i++) {
            float4 v = src[i * 32 + lane];
            a0 = fmaf(v.x, w0[i].x, a0);
            a0 = fmaf(v.y, w0[i].y, a0);
            a0 = fmaf(v.z, w0[i].z, a0);
            a0 = fmaf(v.w, w0[i].w, a0);
            a1 = fmaf(v.x, w1[i].x, a1);
            a1 = fmaf(v.y, w1[i].y, a1);
            a1 = fmaf(v.z, w1[i].z, a1);
            a1 = fmaf(v.w, w1[i].w, a1);
        }

        // Refill the consumed stage immediately (before the reduce chain) so
        // the next tile's DRAM fetch overlaps the shuffle latency.
        if (k + NSTAGES < kmax) issue(k + NSTAGES, st); else cp_commit();

        #pragma unroll
        for (int off = 16; off > 0; off >>= 1) {
            a0 += __shfl_xor_sync(0xFFFFFFFFu, a0, off);
            a1 += __shfl_xor_sync(0xFFFFFFFFu, a1, off);
        }
        if (lane == 0) {
            float mu  = a0;
            float var = fmaxf(1.0f / (1.0f + __expf(-a1)), EPS_VAR);
            float d   = yv - mu;
            warp_sum += 0.5f * (__logf(var) + d * d / var) + HALF_LOG_2PI;
        }
    }

    if (lane == 0) atomicAdd(&out[n], warp_sum);
}

extern "C" void kernel_launch(void* const* d_in, const int* in_sizes, int n_in,
                              void* d_out, int out_size) {
    // metadata order: y (T*N f32), x (T*N*D f32), W (2*D f32), lens (N i32)
    const float*  y    = (const float*)d_in[0];
    const float4* x4   = (const float4*)d_in[1];
    const float4* W4   = (const float4*)d_in[2];
    const int*    lens = (const int*)d_in[3];
    float*        out  = (float*)d_out;

    // Zero the accumulator via a memset node (cheaper than a kernel node;
    // graph-capturable, no allocation). 0x00 bit pattern == 0.0f.
    cudaMemsetAsync(out, 0, N_DIM * sizeof(float));

    dim3 grid(NBX, N_DIM);
    dim3 block(NTHREADS);
    gnll_kernel<<<grid, block>>>(y, x4, W4, lens, out);
}